// round 17
// baseline (speedup 1.0000x reference)
#include <cuda_runtime.h>
#include <cuda_fp16.h>
#include <cstdint>

#define BDIM 16384
#define CDIM 1024
#define DDIM 128
#define LOG2E 1.4426950408889634f

// ------------------------------- scratch -------------------------------
__device__ float s_theta[BDIM * DDIM];
__device__ float s_phi[BDIM * DDIM];
__device__ float s_g[BDIM * DDIM];
__device__ float s_y[BDIM * DDIM];

__device__ __half s_gw[DDIM * CDIM];
__device__ __half s_thw[DDIM * CDIM];
__device__ __half s_phw[DDIM * CDIM];
__device__ __half s_Ww[CDIM * DDIM];

// ------------------------------- helpers -------------------------------
__device__ __forceinline__ unsigned pkh(__half a, __half b) {
    return (unsigned)__half_as_ushort(a) | ((unsigned)__half_as_ushort(b) << 16);
}
__device__ __forceinline__ void ldsm4(uint32_t* r, uint32_t addr) {
    asm volatile("ldmatrix.sync.aligned.m8n8.x4.shared.b16 {%0,%1,%2,%3}, [%4];"
                 : "=r"(r[0]), "=r"(r[1]), "=r"(r[2]), "=r"(r[3]) : "r"(addr));
}
__device__ __forceinline__ void mma16816(float* c, const uint32_t* a, uint32_t b0, uint32_t b1) {
    asm volatile(
        "mma.sync.aligned.m16n8k16.row.col.f32.f16.f16.f32 "
        "{%0,%1,%2,%3}, {%4,%5,%6,%7}, {%8,%9}, {%0,%1,%2,%3};"
        : "+f"(c[0]), "+f"(c[1]), "+f"(c[2]), "+f"(c[3])
        : "r"(a[0]), "r"(a[1]), "r"(a[2]), "r"(a[3]), "r"(b0), "r"(b1));
}
__device__ __forceinline__ void cp16(uint32_t dst, const void* src) {
    asm volatile("cp.async.cg.shared.global [%0], [%1], 16;" :: "r"(dst), "l"(src));
}
#define CP_COMMIT() asm volatile("cp.async.commit_group;")
#define CP_WAIT0()  asm volatile("cp.async.wait_group 0;")
__device__ __forceinline__ float ex2f(float x) {
    float r; asm("ex2.approx.ftz.f32 %0, %1;" : "=f"(r) : "f"(x)); return r;
}

// ---------------- fused weight fp16 convert (4 weights, one launch) ----------------
__global__ void split4_kernel(const float* __restrict__ w0, const float* __restrict__ w1,
                              const float* __restrict__ w2, const float* __restrict__ w3) {
    int wsel = blockIdx.y;
    const float* in = wsel == 0 ? w0 : wsel == 1 ? w1 : wsel == 2 ? w2 : w3;
    __half* hp = wsel == 0 ? s_gw : wsel == 1 ? s_thw : wsel == 2 ? s_phw : s_Ww;
    const int n4 = DDIM * CDIM / 4;
    const float4* in4 = reinterpret_cast<const float4*>(in);
    uint2* h2 = reinterpret_cast<uint2*>(hp);
    for (int i = blockIdx.x * blockDim.x + threadIdx.x; i < n4; i += gridDim.x * blockDim.x) {
        float4 v = in4[i];
        h2[i] = make_uint2(pkh(__float2half_rn(v.x), __float2half_rn(v.y)),
                           pkh(__float2half_rn(v.z), __float2half_rn(v.w)));
    }
}

// ---------------- BK=32 single-sync mainloop (R16-proven; used by out_gemm) ----------------
#define SAP 40
#define oWP 20480u

__device__ __forceinline__ void gemm_mainloop_p(
    const float* __restrict__ A, int K, int NC,
    const __half* __restrict__ W, unsigned char* smem, float acc[2][8][4]) {
    const int tid = threadIdx.x, lane = tid & 31, wid = tid >> 5;
    const int wm = (wid & 3) * 32, wn = (wid >> 2) * 64;
    const uint32_t sbase = (uint32_t)__cvta_generic_to_shared(smem);

    float4 stage[4];
    {
#pragma unroll
        for (int i = 0; i < 4; i++) {
            int q = tid + 256 * i;
            stage[i] = *reinterpret_cast<const float4*>(
                &A[(size_t)(q >> 3) * K + (q & 7) * 4]);
        }
#pragma unroll
        for (int i = 0; i < 2; i++) {
            int q = tid + 256 * i;
            int r = q >> 2, cc = q & 3;
            cp16(sbase + oWP + (uint32_t)(r * SAP + cc * 8) * 2,
                 W + (size_t)r * K + cc * 8);
        }
        CP_COMMIT();
    }

    for (int c = 0; c < NC; c++) {
        const uint32_t abuf = (uint32_t)(c & 1) * 10240u;
#pragma unroll
        for (int i = 0; i < 4; i++) {
            int q = tid + 256 * i;
            int r = q >> 3, c4 = q & 7;
            float4 v = stage[i];
            *reinterpret_cast<uint2*>(smem + abuf + (size_t)(r * SAP + c4 * 4) * 2) =
                make_uint2(pkh(__float2half_rn(v.x), __float2half_rn(v.y)),
                           pkh(__float2half_rn(v.z), __float2half_rn(v.w)));
        }
        if (c + 1 < NC) {
            int kk = (c + 1) * 32;
#pragma unroll
            for (int i = 0; i < 4; i++) {
                int q = tid + 256 * i;
                stage[i] = *reinterpret_cast<const float4*>(
                    &A[(size_t)(q >> 3) * K + kk + (q & 7) * 4]);
            }
        }
        CP_WAIT0();
        __syncthreads();
        if (c + 1 < NC) {
            int kk = (c + 1) * 32;
            uint32_t wdst = sbase + oWP + (uint32_t)((c + 1) & 1) * 10240u;
#pragma unroll
            for (int i = 0; i < 2; i++) {
                int q = tid + 256 * i;
                int r = q >> 2, cc = q & 3;
                cp16(wdst + (uint32_t)(r * SAP + cc * 8) * 2,
                     W + (size_t)r * K + kk + cc * 8);
            }
            CP_COMMIT();
        }
        const uint32_t wb = sbase + oWP + (uint32_t)(c & 1) * 10240u;
#pragma unroll
        for (int ks = 0; ks < 2; ks++) {
            uint32_t ah[2][4], wf[4][4];
#pragma unroll
            for (int mt = 0; mt < 2; mt++) {
                uint32_t aoff = (uint32_t)((wm + mt * 16 + (lane & 15)) * SAP +
                                           ks * 16 + (lane >> 4) * 8) * 2;
                ldsm4(ah[mt], sbase + abuf + aoff);
            }
#pragma unroll
            for (int p = 0; p < 4; p++) {
                uint32_t woff = (uint32_t)((wn + p * 16 + (lane & 7) + ((lane >> 4) & 1) * 8) * SAP +
                                           ks * 16 + ((lane >> 3) & 1) * 8) * 2;
                ldsm4(wf[p], wb + woff);
            }
#pragma unroll
            for (int mt = 0; mt < 2; mt++)
#pragma unroll
                for (int p = 0; p < 4; p++) {
                    mma16816(acc[mt][2 * p], ah[mt], wf[p][0], wf[p][1]);
                    mma16816(acc[mt][2 * p + 1], ah[mt], wf[p][2], wf[p][3]);
                }
        }
    }
}

// ---------------- BK=64 single-sync mainloop (proj) ----------------
// Rows padded to 72 elems (144B): ldsm rows mod 128B = {0,16,...,112} conflict-free.
// smem: A 2x18432 | W 2x18432 = 73728.
#define SAP64 72
#define ABUF64 18432u
#define oW64 36864u
#define PSMEM 73728

__device__ __forceinline__ void gemm_mainloop_p64(
    const float* __restrict__ A, int K, int NC,
    const __half* __restrict__ W, unsigned char* smem, float acc[2][8][4]) {
    const int tid = threadIdx.x, lane = tid & 31, wid = tid >> 5;
    const int wm = (wid & 3) * 32, wn = (wid >> 2) * 64;
    const uint32_t sbase = (uint32_t)__cvta_generic_to_shared(smem);

    float4 stage[8];
    {
#pragma unroll
        for (int i = 0; i < 8; i++) {
            int q = tid + 256 * i;                 // 2048 float4 = 128 rows x 16
            stage[i] = *reinterpret_cast<const float4*>(
                &A[(size_t)(q >> 4) * K + (q & 15) * 4]);
        }
#pragma unroll
        for (int i = 0; i < 4; i++) {
            int q = tid + 256 * i;                 // 1024 cp16 = 128 rows x 8
            int r = q >> 3, cc = q & 7;
            cp16(sbase + oW64 + (uint32_t)(r * SAP64 + cc * 8) * 2,
                 W + (size_t)r * K + cc * 8);
        }
        CP_COMMIT();
    }

    for (int c = 0; c < NC; c++) {
        const uint32_t abuf = (uint32_t)(c & 1) * ABUF64;
        // STS A(c)
#pragma unroll
        for (int i = 0; i < 8; i++) {
            int q = tid + 256 * i;
            int r = q >> 4, c4 = q & 15;
            float4 v = stage[i];
            *reinterpret_cast<uint2*>(smem + abuf + (size_t)(r * SAP64 + c4 * 4) * 2) =
                make_uint2(pkh(__float2half_rn(v.x), __float2half_rn(v.y)),
                           pkh(__float2half_rn(v.z), __float2half_rn(v.w)));
        }
        // stage A(c+1)
        if (c + 1 < NC) {
            int kk = (c + 1) * 64;
#pragma unroll
            for (int i = 0; i < 8; i++) {
                int q = tid + 256 * i;
                stage[i] = *reinterpret_cast<const float4*>(
                    &A[(size_t)(q >> 4) * K + kk + (q & 15) * 4]);
            }
        }
        CP_WAIT0();
        __syncthreads();
        // cp W(c+1)
        if (c + 1 < NC) {
            int kk = (c + 1) * 64;
            uint32_t wdst = sbase + oW64 + (uint32_t)((c + 1) & 1) * ABUF64;
#pragma unroll
            for (int i = 0; i < 4; i++) {
                int q = tid + 256 * i;
                int r = q >> 3, cc = q & 7;
                cp16(wdst + (uint32_t)(r * SAP64 + cc * 8) * 2,
                     W + (size_t)r * K + kk + cc * 8);
            }
            CP_COMMIT();
        }
        // MMA: 4 k-steps
        const uint32_t wb = sbase + oW64 + (uint32_t)(c & 1) * ABUF64;
#pragma unroll
        for (int ks = 0; ks < 4; ks++) {
            uint32_t ah[2][4], wf[4][4];
#pragma unroll
            for (int mt = 0; mt < 2; mt++) {
                uint32_t aoff = (uint32_t)((wm + mt * 16 + (lane & 15)) * SAP64 +
                                           ks * 16 + (lane >> 4) * 8) * 2;
                ldsm4(ah[mt], sbase + abuf + aoff);
            }
#pragma unroll
            for (int p = 0; p < 4; p++) {
                uint32_t woff = (uint32_t)((wn + p * 16 + (lane & 7) + ((lane >> 4) & 1) * 8) * SAP64 +
                                           ks * 16 + ((lane >> 3) & 1) * 8) * 2;
                ldsm4(wf[p], wb + woff);
            }
#pragma unroll
            for (int mt = 0; mt < 2; mt++)
#pragma unroll
                for (int p = 0; p < 4; p++) {
                    mma16816(acc[mt][2 * p], ah[mt], wf[p][0], wf[p][1]);
                    mma16816(acc[mt][2 * p + 1], ah[mt], wf[p][2], wf[p][3]);
                }
        }
    }
}

// grid (3, 128): x = {g, theta, phi}, y = row tile. BK=64 single-sync loop.
__global__ void __launch_bounds__(256)
proj_gemm(const float* __restrict__ x0, const float* __restrict__ x1,
          const float* __restrict__ gb, const float* __restrict__ thb,
          const float* __restrict__ phb) {
    extern __shared__ unsigned char smem[];
    int bz = blockIdx.x;
    size_t bm = (size_t)blockIdx.y * 128;
    const float* A = (bz == 0 ? x0 : x1) + bm * CDIM;
    const __half* W = bz == 0 ? s_gw : bz == 1 ? s_thw : s_phw;
    const float* bias = bz == 0 ? gb : bz == 1 ? thb : phb;
    float* out = (bz == 0 ? s_g : bz == 1 ? s_theta : s_phi) + bm * DDIM;

    float acc[2][8][4];
#pragma unroll
    for (int a = 0; a < 2; a++)
#pragma unroll
        for (int b = 0; b < 8; b++)
#pragma unroll
            for (int c = 0; c < 4; c++) acc[a][b][c] = 0.f;

    gemm_mainloop_p64(A, CDIM, 16, W, smem, acc);

    const int lane = threadIdx.x & 31, wid = threadIdx.x >> 5;
    const int wm = (wid & 3) * 32, wn = (wid >> 2) * 64;
#pragma unroll
    for (int mt = 0; mt < 2; mt++) {
        int r0 = wm + mt * 16 + (lane >> 2);
#pragma unroll
        for (int nt = 0; nt < 8; nt++) {
            int ccol = wn + nt * 8 + (lane & 3) * 2;
            float2 v0 = make_float2(acc[mt][nt][0] + bias[ccol], acc[mt][nt][1] + bias[ccol + 1]);
            float2 v1 = make_float2(acc[mt][nt][2] + bias[ccol], acc[mt][nt][3] + bias[ccol + 1]);
            *reinterpret_cast<float2*>(&out[(size_t)r0 * DDIM + ccol]) = v0;
            *reinterpret_cast<float2*>(&out[(size_t)(r0 + 8) * DDIM + ccol]) = v1;
        }
    }
}

// ---------------- out GEMM: single-sync mainloop + epilogue stage overlapping smem ----------------
#define EPS 132
#define OUT_SMEM (128 * EPS * 4)   // 67584; mainloop uses first 40960, stage reuses from 0

__global__ void __launch_bounds__(256, 2)
out_gemm(const float* __restrict__ Wb, const float* __restrict__ x0, float* __restrict__ out) {
    extern __shared__ unsigned char smem[];
    size_t n0 = (size_t)blockIdx.x * 128;
    size_t bm = (size_t)blockIdx.y * 128;
    const float* A = s_y + bm * DDIM;
    const __half* W = s_Ww + n0 * DDIM;
    const float* resid = x0 + bm * CDIM + n0;
    float* outp = out + bm * CDIM + n0;
    const float* bias = Wb + n0;

    float acc[2][8][4];
#pragma unroll
    for (int a = 0; a < 2; a++)
#pragma unroll
        for (int b = 0; b < 8; b++)
#pragma unroll
            for (int c = 0; c < 4; c++) acc[a][b][c] = 0.f;

    gemm_mainloop_p(A, DDIM, 4, W, smem, acc);
    __syncthreads();   // all warps done reading A/W smem before stage overwrites it

    float* ep = reinterpret_cast<float*>(smem);
    const int tid = threadIdx.x, lane = tid & 31, wid = tid >> 5;
    const int wm = (wid & 3) * 32, wn = (wid >> 2) * 64;
#pragma unroll
    for (int mt = 0; mt < 2; mt++) {
        int r0 = wm + mt * 16 + (lane >> 2);
#pragma unroll
        for (int nt = 0; nt < 8; nt++) {
            int ccol = wn + nt * 8 + (lane & 3) * 2;
            *reinterpret_cast<float2*>(&ep[r0 * EPS + ccol]) =
                make_float2(acc[mt][nt][0], acc[mt][nt][1]);
            *reinterpret_cast<float2*>(&ep[(r0 + 8) * EPS + ccol]) =
                make_float2(acc[mt][nt][2], acc[mt][nt][3]);
        }
    }
    __syncthreads();

#pragma unroll
    for (int i = 0; i < 16; i++) {
        int idx = tid + 256 * i;
        int row = idx >> 5, c4 = (idx & 31) * 4;
        float4 v = *reinterpret_cast<const float4*>(&ep[row * EPS + c4]);
        float4 bv = *reinterpret_cast<const float4*>(&bias[c4]);
        float4 rv = *reinterpret_cast<const float4*>(&resid[(size_t)row * CDIM + c4]);
        v.x += bv.x + rv.x; v.y += bv.y + rv.y;
        v.z += bv.z + rv.z; v.w += bv.w + rv.w;
        *reinterpret_cast<float4*>(&outp[(size_t)row * CDIM + c4]) = v;
    }
}

// ---------------- rank-1 softmax attention (R10-proven pure ex2f) ----------------
__global__ void __launch_bounds__(512)
attn16_kernel() {
    __shared__ float sth[16 * 128], sg[16 * 128], sph[16 * 128];
    const int tid = threadIdx.x;
    const size_t base = (size_t)blockIdx.x * 16 * 128;
    reinterpret_cast<float4*>(sth)[tid] = reinterpret_cast<const float4*>(s_theta + base)[tid];
    reinterpret_cast<float4*>(sg)[tid]  = reinterpret_cast<const float4*>(s_g + base)[tid];
    reinterpret_cast<float4*>(sph)[tid] = reinterpret_cast<const float4*>(s_phi + base)[tid];
    __syncwarp();

    const int w = tid >> 5, l = tid & 31;
    const float* th = sth + w * 128;
    const float* gg = sg + w * 128;
    const float* ph = sph + w * 128;

    float a0 = th[l], a1 = th[l + 32], a2 = th[l + 64], a3 = th[l + 96];
    float mx = fmaxf(fmaxf(a0, a1), fmaxf(a2, a3));
    float mn = fminf(fminf(a0, a1), fminf(a2, a3));
#pragma unroll
    for (int off = 16; off >= 1; off >>= 1) {
        mx = fmaxf(mx, __shfl_xor_sync(0xffffffffu, mx, off));
        mn = fminf(mn, __shfl_xor_sync(0xffffffffu, mn, off));
    }
    float sc[4], m2n[4], num[4], den[4];
#pragma unroll
    for (int q = 0; q < 4; q++) {
        sc[q] = ph[l + 32 * q] * LOG2E;
        m2n[q] = -sc[q] * (sc[q] >= 0.f ? mx : mn);
        num[q] = 0.f; den[q] = 0.f;
    }
#pragma unroll 8
    for (int j = 0; j < 128; j += 4) {
        float4 tv = *reinterpret_cast<const float4*>(&th[j]);
        float4 gv = *reinterpret_cast<const float4*>(&gg[j]);
        float t_[4] = {tv.x, tv.y, tv.z, tv.w};
        float g_[4] = {gv.x, gv.y, gv.z, gv.w};
#pragma unroll
        for (int e = 0; e < 4; e++) {
#pragma unroll
            for (int q = 0; q < 4; q++) {
                float ex = ex2f(fmaf(sc[q], t_[e], m2n[q]));
                num[q] = fmaf(ex, g_[e], num[q]);
                den[q] += ex;
            }
        }
    }
#pragma unroll
    for (int q = 0; q < 4; q++)
        s_y[base + (size_t)w * 128 + l + 32 * q] = num[q] / den[q];
}

// ------------------------------- launch -------------------------------
extern "C" void kernel_launch(void* const* d_in, const int* in_sizes, int n_in,
                              void* d_out, int out_size) {
    const float* x0   = (const float*)d_in[0];
    const float* x1   = (const float*)d_in[1];
    const float* g_w  = (const float*)d_in[2];
    const float* g_b  = (const float*)d_in[3];
    const float* th_w = (const float*)d_in[4];
    const float* th_b = (const float*)d_in[5];
    const float* ph_w = (const float*)d_in[6];
    const float* ph_b = (const float*)d_in[7];
    const float* W_w  = (const float*)d_in[8];
    const float* W_b  = (const float*)d_in[9];
    float* out = (float*)d_out;

    cudaFuncSetAttribute(out_gemm, cudaFuncAttributeMaxDynamicSharedMemorySize, OUT_SMEM);
    cudaFuncSetAttribute(proj_gemm, cudaFuncAttributeMaxDynamicSharedMemorySize, PSMEM);

    split4_kernel<<<dim3(32, 4), 256>>>(g_w, th_w, ph_w, W_w);

    proj_gemm<<<dim3(3, BDIM / 128), 256, PSMEM>>>(x0, x1, g_b, th_b, ph_b);

    attn16_kernel<<<BDIM / 16, 512>>>();

    out_gemm<<<dim3(8, BDIM / 128), 256, OUT_SMEM>>>(W_b, x0, out);
}